// round 1
// baseline (speedup 1.0000x reference)
#include <cuda_runtime.h>
#include <cstdint>

#define B_SZ   16
#define C_IN   64
#define N_POS  40962
#define C_OUT  32
#define K_CH   224                 // 7*C_OUT, permuted: k = sub*32 + o
#define NEW_N  (4*N_POS - 6)       // 163842
#define SEVEN_N (7*N_POS)

typedef unsigned long long ull;

// 587 MB scratch for y' [B][N][224] (permuted channel layout)
__device__ float g_y[(size_t)B_SZ * N_POS * K_CH];

__device__ __forceinline__ ull dup2(float w) {
    unsigned u = __float_as_uint(w);
    ull r;
    asm("mov.b64 %0, {%1, %1};" : "=l"(r) : "r"(u));
    return r;
}
__device__ __forceinline__ void ffma2(ull &d, ull a, ull b) {
    asm("fma.rn.f32x2 %0, %1, %2, %0;" : "+l"(d) : "l"(a), "l"(b));
}
__device__ __forceinline__ float lo32(ull v) { return __uint_as_float((unsigned)(v & 0xffffffffull)); }
__device__ __forceinline__ float hi32(ull v) { return __uint_as_float((unsigned)(v >> 32)); }

// ---------------------------------------------------------------------------
// Kernel 1: y'[b][p][k] = sum_c x[b][c][p] * W[(k%32)*7 + k/32][c] + bias(k)
// Tile: 128 p  x  224 k, K=64 entirely in smem. 256 threads.
// Thread micro-tile: 8 p (as 4 f32x2 pairs) x 14 k. FFMA2 packed math.
// ---------------------------------------------------------------------------
#define TP 128
#define BS_STRIDE 225   // pad to kill STS bank conflicts

__global__ __launch_bounds__(256, 1)
void gemm_perm_kernel(const float* __restrict__ x,
                      const float* __restrict__ W,
                      const float* __restrict__ bias)
{
    extern __shared__ float sh[];
    float* As = sh;                         // [64][128]
    float* Bs = sh + C_IN * TP;             // [64][225]
    float* bS = Bs + C_IN * BS_STRIDE;      // [224]

    const int b   = blockIdx.y;
    const int p0  = blockIdx.x * TP;
    const int tid = threadIdx.x;

    // Load W permuted: Bs[c][k] = W[((k%32)*7 + k/32)*64 + c]  (gmem coalesced in c)
    for (int idx = tid; idx < K_CH * C_IN; idx += 256) {
        int k = idx >> 6;          // /64
        int c = idx & 63;
        int rw = (k & 31) * 7 + (k >> 5);
        Bs[c * BS_STRIDE + k] = W[rw * C_IN + c];
    }
    if (tid < K_CH) {
        int rw = (tid & 31) * 7 + (tid >> 5);
        bS[tid] = bias[rw];
    }
    // Load A tile: As[c][p] = x[b][c][p0+p]
    const float* xb = x + (size_t)b * C_IN * N_POS;
    for (int idx = tid; idx < C_IN * TP; idx += 256) {
        int c = idx >> 7;          // /128
        int p = idx & 127;
        int gp = p0 + p;
        As[idx] = (gp < N_POS) ? xb[(size_t)c * N_POS + gp] : 0.0f;
    }
    __syncthreads();

    const int kg = tid & 15;       // k-group: 14 channels
    const int pg = tid >> 4;       // p-group: 8 positions (4 pairs)
    const int k0 = kg * 14;

    ull acc[4][14];
    #pragma unroll
    for (int kk = 0; kk < 14; kk++) {
        ull bz = dup2(bS[k0 + kk]);
        acc[0][kk] = bz; acc[1][kk] = bz; acc[2][kk] = bz; acc[3][kk] = bz;
    }

    const float* Aptr = As + pg * 8;
    const float* Bptr = Bs + k0;

    #pragma unroll 8
    for (int c = 0; c < C_IN; c++) {
        const ulonglong2* ap = (const ulonglong2*)(Aptr + c * TP);
        ulonglong2 a01 = ap[0];
        ulonglong2 a23 = ap[1];
        ull a0 = a01.x, a1 = a01.y, a2 = a23.x, a3 = a23.y;
        const float* bp = Bptr + c * BS_STRIDE;
        #pragma unroll
        for (int kk = 0; kk < 14; kk++) {
            ull bw = dup2(bp[kk]);
            ffma2(acc[0][kk], a0, bw);
            ffma2(acc[1][kk], a1, bw);
            ffma2(acc[2][kk], a2, bw);
            ffma2(acc[3][kk], a3, bw);
        }
    }

    // Epilogue: y'[b][p][k0..k0+13]
    float* yb = g_y + ((size_t)b * N_POS) * K_CH;
    #pragma unroll
    for (int j = 0; j < 4; j++) {
        int p = p0 + pg * 8 + 2 * j;
        if (p < N_POS) {
            float* yr = yb + (size_t)p * K_CH + k0;
            #pragma unroll
            for (int kk = 0; kk < 14; kk++) yr[kk] = lo32(acc[j][kk]);
        }
        if (p + 1 < N_POS) {
            float* yr = yb + (size_t)(p + 1) * K_CH + k0;
            #pragma unroll
            for (int kk = 0; kk < 14; kk++) yr[kk] = hi32(acc[j][kk]);
        }
    }
}

// ---------------------------------------------------------------------------
// Kernel 2: gather + pair-average + transpose for coalesced output writes.
// CTA: one b, 64 m positions. Warp per m (uniform branch), lane = o channel:
// reads y'[b][p][sub*32 + lane] -> 128B contiguous per warp.
// ---------------------------------------------------------------------------
#define GM 64

__global__ __launch_bounds__(256)
void gather_kernel(const int* __restrict__ top,
                   const int* __restrict__ down,
                   float* __restrict__ out)
{
    __shared__ float sm[GM][33];
    const int b    = blockIdx.y;
    const int m0   = blockIdx.x * GM;
    const int lane = threadIdx.x & 31;
    const int w    = threadIdx.x >> 5;   // 0..7

    const float* yb = g_y + (size_t)b * N_POS * K_CH;

    #pragma unroll
    for (int i = 0; i < 8; i++) {
        int mm = w * 8 + i;
        int m  = m0 + mm;
        float v = 0.0f;
        if (m < NEW_N) {
            if (m < N_POS) {
                int j   = top[m];
                int sub = j / N_POS;
                int p   = j - sub * N_POS;
                v = yb[(size_t)p * K_CH + sub * 32 + lane];
            } else {
                int i2 = m - N_POS;
                int j0 = down[2 * i2];
                int j1 = down[2 * i2 + 1];
                int s0 = j0 / N_POS, p0i = j0 - s0 * N_POS;
                int s1 = j1 / N_POS, p1i = j1 - s1 * N_POS;
                float v0 = yb[(size_t)p0i * K_CH + s0 * 32 + lane];
                float v1 = yb[(size_t)p1i * K_CH + s1 * 32 + lane];
                v = 0.5f * (v0 + v1);
            }
        }
        sm[mm][lane] = v;
    }
    __syncthreads();

    // out[b][o][m0+mm], coalesced along mm
    float* ob = out + (size_t)b * C_OUT * NEW_N;
    for (int idx = threadIdx.x; idx < C_OUT * GM; idx += 256) {
        int o  = idx >> 6;   // /64
        int mm = idx & 63;
        int m  = m0 + mm;
        if (m < NEW_N) ob[(size_t)o * NEW_N + m] = sm[mm][o];
    }
}

// ---------------------------------------------------------------------------
extern "C" void kernel_launch(void* const* d_in, const int* in_sizes, int n_in,
                              void* d_out, int out_size)
{
    const float* x    = (const float*)d_in[0];
    const float* W    = (const float*)d_in[1];
    const float* bias = (const float*)d_in[2];
    const int*   top  = (const int*)d_in[3];
    const int*   down = (const int*)d_in[4];
    float* out = (float*)d_out;

    const int smem = (C_IN * TP + C_IN * BS_STRIDE + K_CH) * sizeof(float); // 91264 B
    cudaFuncSetAttribute(gemm_perm_kernel,
                         cudaFuncAttributeMaxDynamicSharedMemorySize, smem);

    dim3 g1((N_POS + TP - 1) / TP, B_SZ);   // (321, 16)
    gemm_perm_kernel<<<g1, 256, smem>>>(x, W, bias);

    dim3 g2((NEW_N + GM - 1) / GM, B_SZ);   // (2561, 16)
    gather_kernel<<<g2, 256>>>(top, down, out);
}

// round 2
// speedup vs baseline: 1.3975x; 1.3975x over previous
#include <cuda_runtime.h>
#include <cstdint>

#define B_SZ   16
#define C_IN   64
#define N_POS  40962
#define C_OUT  32
#define K_CH   224                 // 7*C_OUT, permuted: k = sub*32 + o
#define NEW_N  (4*N_POS - 6)       // 163842

typedef unsigned long long ull;

// 587 MB scratch for y' [B][N][224] (permuted channel layout)
__device__ float g_y[(size_t)B_SZ * N_POS * K_CH];

__device__ __forceinline__ ull dup2(float w) {
    unsigned u = __float_as_uint(w);
    ull r;
    asm("mov.b64 %0, {%1, %1};" : "=l"(r) : "r"(u));
    return r;
}
__device__ __forceinline__ void ffma2(ull &d, ull a, ull b) {
    asm("fma.rn.f32x2 %0, %1, %2, %0;" : "+l"(d) : "l"(a), "l"(b));
}
__device__ __forceinline__ float lo32(ull v) { return __uint_as_float((unsigned)(v & 0xffffffffull)); }
__device__ __forceinline__ float hi32(ull v) { return __uint_as_float((unsigned)(v >> 32)); }

// ---------------------------------------------------------------------------
// Kernel 1: y'[b][p][k] = sum_c x[b][c][p] * W[(k%32)*7 + k/32][c] + bias(k)
// Tile: 128 p x 224 k (two passes of 112 k). 256 threads, 2 CTAs/SM.
// Thread micro-tile per pass: 8 p (4 f32x2 pairs) x 7 k. 28 FFMA2 per c.
// B operand pre-duplicated in smem as (w,w) 64-bit pairs -> no dup movs.
// ---------------------------------------------------------------------------
#define TP 128
#define TK 112
#define BSD_STRIDE 113   // ull stride pad: kills 32-way STS conflict in build

__global__ __launch_bounds__(256, 2)
void gemm_perm_kernel(const float* __restrict__ x,
                      const float* __restrict__ W,
                      const float* __restrict__ bias)
{
    extern __shared__ float sh[];
    float* As  = sh;                               // [64][128]  32 KB
    ull*   Bsd = (ull*)(sh + C_IN * TP);           // [64][113]  57.9 KB
    float* bS  = (float*)(Bsd + C_IN * BSD_STRIDE);// [112]

    const int b   = blockIdx.y;
    const int p0  = blockIdx.x * TP;
    const int tid = threadIdx.x;

    // Load A tile once: As[c][p] = x[b][c][p0+p]
    const float* xb = x + (size_t)b * C_IN * N_POS;
    for (int idx = tid; idx < C_IN * TP; idx += 256) {
        int c = idx >> 7;          // /128
        int p = idx & 127;
        int gp = p0 + p;
        As[idx] = (gp < N_POS) ? xb[(size_t)c * N_POS + gp] : 0.0f;
    }

    const int kg = tid & 15;       // k-group: 7 channels
    const int pg = tid >> 4;       // p-group: 8 positions (4 pairs)
    const int k0 = kg * 7;

    float* yb = g_y + (size_t)b * N_POS * K_CH;

    for (int h = 0; h < 2; h++) {
        const int kbase = h * TK;
        __syncthreads();   // pass>0: previous pass done reading Bsd

        // Build pre-duplicated B: Bsd[c][k'] = dup(W[rw*64+c]), coalesced in c.
        for (int idx = tid; idx < C_IN * TK; idx += 256) {
            int k = idx >> 6;            // 0..111 (k' within pass)
            int c = idx & 63;
            int kglob = kbase + k;
            int rw = (kglob & 31) * 7 + (kglob >> 5);
            Bsd[c * BSD_STRIDE + k] = dup2(W[rw * C_IN + c]);
        }
        if (tid < TK) {
            int kglob = kbase + tid;
            int rw = (kglob & 31) * 7 + (kglob >> 5);
            bS[tid] = bias[rw];
        }
        __syncthreads();

        ull acc[4][7];
        #pragma unroll
        for (int kk = 0; kk < 7; kk++) {
            ull bz = dup2(bS[k0 + kk]);
            acc[0][kk] = bz; acc[1][kk] = bz; acc[2][kk] = bz; acc[3][kk] = bz;
        }

        const float* Aptr = As + pg * 8;
        const ull*   Bptr = Bsd + k0;

        #pragma unroll 4
        for (int c = 0; c < C_IN; c++) {
            const ulonglong2* ap = (const ulonglong2*)(Aptr + c * TP);
            ulonglong2 a01 = ap[0];
            ulonglong2 a23 = ap[1];
            const ull* bp = Bptr + c * BSD_STRIDE;
            #pragma unroll
            for (int kk = 0; kk < 7; kk++) {
                ull bw = bp[kk];
                ffma2(acc[0][kk], a01.x, bw);
                ffma2(acc[1][kk], a01.y, bw);
                ffma2(acc[2][kk], a23.x, bw);
                ffma2(acc[3][kk], a23.y, bw);
            }
        }

        // Epilogue: y'[b][p][kbase + k0 .. +6]
        #pragma unroll
        for (int j = 0; j < 4; j++) {
            int p = p0 + pg * 8 + 2 * j;
            if (p < N_POS) {
                float* yr = yb + (size_t)p * K_CH + kbase + k0;
                #pragma unroll
                for (int kk = 0; kk < 7; kk++) yr[kk] = lo32(acc[j][kk]);
            }
            if (p + 1 < N_POS) {
                float* yr = yb + (size_t)(p + 1) * K_CH + kbase + k0;
                #pragma unroll
                for (int kk = 0; kk < 7; kk++) yr[kk] = hi32(acc[j][kk]);
            }
        }
    }
}

// ---------------------------------------------------------------------------
// Kernel 2: gather + pair-average + transpose for coalesced output writes.
// Warp per m (uniform branch), lane = o channel: 128B coalesced random read.
// ---------------------------------------------------------------------------
#define GM 64

__global__ __launch_bounds__(256)
void gather_kernel(const int* __restrict__ top,
                   const int* __restrict__ down,
                   float* __restrict__ out)
{
    __shared__ float sm[GM][33];
    const int b    = blockIdx.y;
    const int m0   = blockIdx.x * GM;
    const int lane = threadIdx.x & 31;
    const int w    = threadIdx.x >> 5;   // 0..7

    const float* yb = g_y + (size_t)b * N_POS * K_CH;

    #pragma unroll
    for (int i = 0; i < 8; i++) {
        int mm = w * 8 + i;
        int m  = m0 + mm;
        float v = 0.0f;
        if (m < NEW_N) {
            if (m < N_POS) {
                int j   = top[m];
                int sub = j / N_POS;
                int p   = j - sub * N_POS;
                v = yb[(size_t)p * K_CH + sub * 32 + lane];
            } else {
                int i2 = m - N_POS;
                int j0 = down[2 * i2];
                int j1 = down[2 * i2 + 1];
                int s0 = j0 / N_POS, p0i = j0 - s0 * N_POS;
                int s1 = j1 / N_POS, p1i = j1 - s1 * N_POS;
                float v0 = yb[(size_t)p0i * K_CH + s0 * 32 + lane];
                float v1 = yb[(size_t)p1i * K_CH + s1 * 32 + lane];
                v = 0.5f * (v0 + v1);
            }
        }
        sm[mm][lane] = v;
    }
    __syncthreads();

    // out[b][o][m0+mm], coalesced along mm
    float* ob = out + (size_t)b * C_OUT * NEW_N;
    for (int idx = threadIdx.x; idx < C_OUT * GM; idx += 256) {
        int o  = idx >> 6;   // /64
        int mm = idx & 63;
        int m  = m0 + mm;
        if (m < NEW_N) ob[(size_t)o * NEW_N + m] = sm[mm][o];
    }
}

// ---------------------------------------------------------------------------
extern "C" void kernel_launch(void* const* d_in, const int* in_sizes, int n_in,
                              void* d_out, int out_size)
{
    const float* x    = (const float*)d_in[0];
    const float* W    = (const float*)d_in[1];
    const float* bias = (const float*)d_in[2];
    const int*   top  = (const int*)d_in[3];
    const int*   down = (const int*)d_in[4];
    float* out = (float*)d_out;

    const int smem = C_IN * TP * 4 + C_IN * BSD_STRIDE * 8 + TK * 4; // 91072 B
    cudaFuncSetAttribute(gemm_perm_kernel,
                         cudaFuncAttributeMaxDynamicSharedMemorySize, smem);

    dim3 g1((N_POS + TP - 1) / TP, B_SZ);   // (321, 16)
    gemm_perm_kernel<<<g1, 256, smem>>>(x, W, bias);

    dim3 g2((NEW_N + GM - 1) / GM, B_SZ);   // (2561, 16)
    gather_kernel<<<g2, 256>>>(top, down, out);
}

// round 3
// speedup vs baseline: 1.7674x; 1.2647x over previous
#include <cuda_runtime.h>
#include <cstdint>

#define B_SZ   16
#define C_IN   64
#define N_POS  40962
#define C_OUT  32
#define K_CH   224                 // 7*C_OUT, permuted: k = sub*32 + o
#define NEW_N  (4*N_POS - 6)       // 163842

typedef unsigned long long ull;

// 587 MB scratch for y' [B][N][224] (permuted channel layout)
__device__ float g_y[(size_t)B_SZ * N_POS * K_CH];

__device__ __forceinline__ ull dup2(float w) {
    unsigned u = __float_as_uint(w);
    ull r;
    asm("mov.b64 %0, {%1, %1};" : "=l"(r) : "r"(u));
    return r;
}
__device__ __forceinline__ void ffma2(ull &d, ull a, ull b) {
    asm("fma.rn.f32x2 %0, %1, %2, %0;" : "+l"(d) : "l"(a), "l"(b));
}
__device__ __forceinline__ float lo32(ull v) { return __uint_as_float((unsigned)(v & 0xffffffffull)); }
__device__ __forceinline__ float hi32(ull v) { return __uint_as_float((unsigned)(v >> 32)); }

// ---------------------------------------------------------------------------
// Kernel 1: y'[b][p][k] = sum_c x[b][c][p] * W[(k%32)*7 + k/32][c] + bias(k)
// Tile: 128 p x 224 k (two passes of 112 k). 256 threads, 2 CTAs/SM.
// Thread micro-tile per pass: 8 p (4 f32x2 pairs) x 7 k. 28 FFMA2 per c.
// B pre-duplicated (w,w) pairs in smem; epilogue staged through smem so
// global stores are LDS.128 + STG.128 (4 wavefronts/STG instead of ~8).
// ---------------------------------------------------------------------------
#define TP 128
#define TK 112
#define BSD_STRIDE 113   // ull stride pad: kills STS conflict in build

__global__ __launch_bounds__(256, 2)
void gemm_perm_kernel(const float* __restrict__ x,
                      const float* __restrict__ W,
                      const float* __restrict__ bias)
{
    extern __shared__ float sh[];
    float* As  = sh;                               // [64][128]  32 KB
    ull*   Bsd = (ull*)(sh + C_IN * TP);           // [64][113]  57.9 KB (union w/ ep)
    float* bS  = (float*)(Bsd + C_IN * BSD_STRIDE);// [112]
    float* ep  = (float*)Bsd;                      // epilogue stage [128][112] = 57.3 KB

    const int b   = blockIdx.y;
    const int p0  = blockIdx.x * TP;
    const int tid = threadIdx.x;
    const int wid = tid >> 5;
    const int ln  = tid & 31;

    // Load A tile once: As[c][p] = x[b][c][p0+p]
    const float* xb = x + (size_t)b * C_IN * N_POS;
    for (int idx = tid; idx < C_IN * TP; idx += 256) {
        int c = idx >> 7;          // /128
        int p = idx & 127;
        int gp = p0 + p;
        As[idx] = (gp < N_POS) ? xb[(size_t)c * N_POS + gp] : 0.0f;
    }

    const int kg = tid & 15;       // k-group: 7 channels
    const int pg = tid >> 4;       // p-group: 8 positions (4 pairs)
    const int k0 = kg * 7;

    float* yb = g_y + (size_t)b * N_POS * K_CH;

    for (int h = 0; h < 2; h++) {
        const int kbase = h * TK;
        __syncthreads();   // prev pass done reading ep/Bsd (and A load done, h=0)

        // Build pre-duplicated B: Bsd[c][k'] = dup(W[rw*64+c]), coalesced in c.
        for (int idx = tid; idx < C_IN * TK; idx += 256) {
            int k = idx >> 6;            // 0..111 (k' within pass)
            int c = idx & 63;
            int kglob = kbase + k;
            int rw = (kglob & 31) * 7 + (kglob >> 5);
            Bsd[c * BSD_STRIDE + k] = dup2(W[rw * C_IN + c]);
        }
        if (tid < TK) {
            int kglob = kbase + tid;
            int rw = (kglob & 31) * 7 + (kglob >> 5);
            bS[tid] = bias[rw];
        }
        __syncthreads();

        ull acc[4][7];
        #pragma unroll
        for (int kk = 0; kk < 7; kk++) {
            ull bz = dup2(bS[k0 + kk]);
            acc[0][kk] = bz; acc[1][kk] = bz; acc[2][kk] = bz; acc[3][kk] = bz;
        }

        const float* Aptr = As + pg * 8;
        const ull*   Bptr = Bsd + k0;

        #pragma unroll 4
        for (int c = 0; c < C_IN; c++) {
            const ulonglong2* ap = (const ulonglong2*)(Aptr + c * TP);
            ulonglong2 a01 = ap[0];
            ulonglong2 a23 = ap[1];
            const ull* bp = Bptr + c * BSD_STRIDE;
            #pragma unroll
            for (int kk = 0; kk < 7; kk++) {
                ull bw = bp[kk];
                ffma2(acc[0][kk], a01.x, bw);
                ffma2(acc[1][kk], a01.y, bw);
                ffma2(acc[2][kk], a23.x, bw);
                ffma2(acc[3][kk], a23.y, bw);
            }
        }

        __syncthreads();   // done reading Bsd; ep may overwrite it

        // Stage accumulators: ep[p_local][k'] (stride 112, 16B-aligned rows)
        #pragma unroll
        for (int j = 0; j < 4; j++) {
            int pl = pg * 8 + 2 * j;
            float* r0 = ep + pl * TK + k0;
            float* r1 = r0 + TK;
            #pragma unroll
            for (int kk = 0; kk < 7; kk++) {
                r0[kk] = lo32(acc[j][kk]);
                r1[kk] = hi32(acc[j][kk]);
            }
        }
        __syncthreads();

        // Coalesced write: warp handles 16 rows, lanes 0-27 write float4 each.
        if (ln < 28) {
            #pragma unroll
            for (int r = 0; r < 16; r++) {
                int row = wid * 16 + r;
                int gp = p0 + row;
                if (gp < N_POS) {
                    float4 v = *(const float4*)(ep + row * TK + ln * 4);
                    *(float4*)(yb + (size_t)gp * K_CH + kbase + ln * 4) = v;
                }
            }
        }
    }
}

// ---------------------------------------------------------------------------
// Kernel 2: gather + pair-average + transpose.
// 8 lanes per m (lane reads float4) -> 4 m per warp-instruction: 4x MLP,
// 4x fewer decode instructions. smem transpose, float2 coalesced output.
// ---------------------------------------------------------------------------
#define GM 256

__global__ __launch_bounds__(256)
void gather_kernel(const int* __restrict__ top,
                   const int* __restrict__ down,
                   float* __restrict__ out)
{
    __shared__ float sm[GM][33];
    const int b    = blockIdx.y;
    const int m0   = blockIdx.x * GM;
    const int tid  = threadIdx.x;
    const int lane = tid & 31;
    const int w    = tid >> 5;     // 0..7
    const int g8   = lane >> 3;    // 0..3 : which m within the quad
    const int l8   = lane & 7;     // 0..7 : float4 slot within 32 channels

    const float* yb = g_y + (size_t)b * N_POS * K_CH;

    #pragma unroll
    for (int i = 0; i < 8; i++) {
        int mm = w * 32 + i * 4 + g8;
        int m  = m0 + mm;
        float4 v = make_float4(0.f, 0.f, 0.f, 0.f);
        if (m < NEW_N) {
            if (m < N_POS) {
                int j   = __ldg(top + m);
                int sub = j / N_POS;
                int p   = j - sub * N_POS;
                v = *(const float4*)(yb + (size_t)p * K_CH + sub * 32 + l8 * 4);
            } else {
                int2 jj = *(const int2*)(down + 2 * (m - N_POS));
                int s0 = jj.x / N_POS, p0i = jj.x - s0 * N_POS;
                int s1 = jj.y / N_POS, p1i = jj.y - s1 * N_POS;
                float4 v0 = *(const float4*)(yb + (size_t)p0i * K_CH + s0 * 32 + l8 * 4);
                float4 v1 = *(const float4*)(yb + (size_t)p1i * K_CH + s1 * 32 + l8 * 4);
                v.x = 0.5f * (v0.x + v1.x);
                v.y = 0.5f * (v0.y + v1.y);
                v.z = 0.5f * (v0.z + v1.z);
                v.w = 0.5f * (v0.w + v1.w);
            }
        }
        // STS: bank = mm + 4*l8 + c (mod 32): g8 + 4*l8 distinct -> conflict-free
        float* s = &sm[mm][l8 * 4];
        s[0] = v.x; s[1] = v.y; s[2] = v.z; s[3] = v.w;
    }
    __syncthreads();

    // out[b][o][m], float2 along m (NEW_N even; 8B alignment guaranteed)
    float* ob = out + (size_t)b * C_OUT * NEW_N;
    #pragma unroll
    for (int it = 0; it < C_OUT * (GM / 2) / 256; it++) {   // 16 iters
        int idx = it * 256 + tid;
        int o = idx >> 7;          // /(GM/2)
        int q = idx & 127;
        int m = m0 + 2 * q;
        if (m < NEW_N) {
            float2 v = make_float2(sm[2 * q][o], sm[2 * q + 1][o]);
            *(float2*)(ob + (size_t)o * NEW_N + m) = v;
        }
    }
}

// ---------------------------------------------------------------------------
extern "C" void kernel_launch(void* const* d_in, const int* in_sizes, int n_in,
                              void* d_out, int out_size)
{
    const float* x    = (const float*)d_in[0];
    const float* W    = (const float*)d_in[1];
    const float* bias = (const float*)d_in[2];
    const int*   top  = (const int*)d_in[3];
    const int*   down = (const int*)d_in[4];
    float* out = (float*)d_out;

    const int smem = C_IN * TP * 4 + C_IN * BSD_STRIDE * 8 + TK * 4; // 91072 B
    cudaFuncSetAttribute(gemm_perm_kernel,
                         cudaFuncAttributeMaxDynamicSharedMemorySize, smem);

    dim3 g1((N_POS + TP - 1) / TP, B_SZ);   // (321, 16)
    gemm_perm_kernel<<<g1, 256, smem>>>(x, W, bias);

    dim3 g2((NEW_N + GM - 1) / GM, B_SZ);   // (641, 16)
    gather_kernel<<<g2, 256>>>(top, down, out);
}

// round 5
// speedup vs baseline: 2.7876x; 1.5772x over previous
#include <cuda_runtime.h>
#include <cstdint>

#define B_SZ    16
#define C_IN    64
#define N_POS   40962
#define C_OUT   32
#define K_CH    224                 // 7*C_OUT, permuted: k = sub*32 + o
#define NEW_N   (4*N_POS - 6)       // 163842
#define TILE_P  128
#define TILES_PER_B 321             // ceil(40962/128)
#define WORK_ITEMS (B_SZ * TILES_PER_B)   // 5136
#define GEMM_GRID 148

// 587 MB scratch for y' [B][N][224] (permuted channel layout)
__device__ float g_y[(size_t)B_SZ * N_POS * K_CH];

// ---------------------------------------------------------------------------
// smem layout (bytes). All bf16 tiles are [row][64] = 128 B/row, SW128 swizzle.
// ---------------------------------------------------------------------------
#define SM_AH   0        // Ah [128][64] bf16 : 16384
#define SM_AL   16384    // Al [128][64] bf16 : 16384
#define SM_WH   32768    // Wh [224][64] bf16 : 28672
#define SM_WL   61440    // Wl [224][64] bf16 : 28672
#define SM_ASF  90112    // x staging f32 [64][128] : 32768
#define SM_TOTAL 122880

static __device__ __forceinline__ uint32_t smem_u32(const void* p) {
    uint32_t a;
    asm("{ .reg .u64 t; cvta.to.shared.u64 t, %1; cvt.u32.u64 %0, t; }" : "=r"(a) : "l"(p));
    return a;
}
static __device__ __forceinline__ uint32_t swz(uint32_t off) {
    return off ^ ((off >> 3) & 0x70);
}
static __device__ __forceinline__ uint32_t bf16x2_of(float hi_f, float lo_f) {
    uint32_t r;
    asm("cvt.rn.bf16x2.f32 %0, %1, %2;" : "=r"(r) : "f"(hi_f), "f"(lo_f));
    return r;
}
static __device__ __forceinline__ void ldsm_x4(uint32_t* a, uint32_t addr) {
    asm volatile("ldmatrix.sync.aligned.m8n8.x4.shared.b16 {%0,%1,%2,%3}, [%4];"
                 : "=r"(a[0]), "=r"(a[1]), "=r"(a[2]), "=r"(a[3]) : "r"(addr));
}
static __device__ __forceinline__ void ldsm_x2(uint32_t* b, uint32_t addr) {
    asm volatile("ldmatrix.sync.aligned.m8n8.x2.shared.b16 {%0,%1}, [%2];"
                 : "=r"(b[0]), "=r"(b[1]) : "r"(addr));
}
static __device__ __forceinline__ void mma_bf16(float* d, const uint32_t* a, const uint32_t* b) {
    asm volatile("mma.sync.aligned.m16n8k16.row.col.f32.bf16.bf16.f32 "
                 "{%0,%1,%2,%3}, {%4,%5,%6,%7}, {%8,%9}, {%0,%1,%2,%3};"
                 : "+f"(d[0]), "+f"(d[1]), "+f"(d[2]), "+f"(d[3])
                 : "r"(a[0]), "r"(a[1]), "r"(a[2]), "r"(a[3]), "r"(b[0]), "r"(b[1]));
}

// ---------------------------------------------------------------------------
// Persistent HMMA GEMM: y'[b][p][n] = sum_c x[b][c][p]*W'[n][c] + bias(n)
// 3xBF16 split over segments s: A = {Ah, Al, Ah}, B = {Wh, Wh, Wl}.
// Warp layout: wm = w&3 -> rows wm*32..+31 (2 m16 tiles); wn = w>>2 -> cols
// wn*112..+111 (14 n8 tiles). Accumulators d[2][14][4] f32.
// ---------------------------------------------------------------------------
__global__ void __launch_bounds__(256, 1)
gemm_hmma_kernel(const float* __restrict__ x,
                 const float* __restrict__ W,
                 const float* __restrict__ bias)
{
    extern __shared__ char sm[];
    const uint32_t smb = smem_u32(sm);
    float* Asf = (float*)(sm + SM_ASF);

    const int tid = threadIdx.x;
    const int w   = tid >> 5;
    const int l   = tid & 31;
    const int wm  = w & 3;
    const int wn  = w >> 2;

    // --- one-time: build Wh/Wl (permuted, bf16 hi/lo, swizzled) ---
    for (int idx = tid; idx < K_CH * C_IN; idx += 256) {
        int n = idx >> 6, c = idx & 63;
        int rw = (n & 31) * 7 + (n >> 5);
        float wv = W[rw * C_IN + c];
        uint32_t hb = bf16x2_of(0.0f, wv);              // low 16 = bf16(wv)
        float hf = __uint_as_float(hb << 16);
        uint32_t lb = bf16x2_of(0.0f, wv - hf);
        uint32_t off = swz((uint32_t)(n * 128 + c * 2));
        *(uint16_t*)(sm + SM_WH + off) = (uint16_t)hb;
        *(uint16_t*)(sm + SM_WL + off) = (uint16_t)lb;
    }

    // --- per-thread bias regs: n = wn*112 + nt*8 + 2*(l&3) ---
    float2 bb[14];
    {
        int nbase = wn * 112 + (l & 3) * 2;
        #pragma unroll
        for (int nt = 0; nt < 14; nt++) {
            int n0 = nbase + nt * 8;
            int r0 = (n0 & 31) * 7 + (n0 >> 5);
            int n1 = n0 + 1;
            int r1 = (n1 & 31) * 7 + (n1 >> 5);
            bb[nt].x = bias[r0];
            bb[nt].y = bias[r1];
        }
    }

    // ldmatrix per-lane base offsets (unswizzled)
    const uint32_t a_lane = (uint32_t)((wm * 32 + (l & 15)) * 128 + (l >> 4) * 16);
    const uint32_t b_lane = (uint32_t)((wn * 112 + (l & 7)) * 128 + ((l >> 3) & 1) * 16);

    // convert-phase mapping: thread -> row p = (w&3)*32 + l, c half (w>>2)*32
    const int cp  = wm * 32 + l;
    const int cc0 = wn * 32;

    for (int item = blockIdx.x; item < WORK_ITEMS; item += GEMM_GRID) {
        const int b  = item / TILES_PER_B;
        const int t  = item - b * TILES_PER_B;
        const int p0 = t * TILE_P;
        float* yb = g_y + (size_t)b * N_POS * K_CH;

        // --- stage x tile: Asf[c][p] ---
        {
            const float* xb = x + (size_t)b * C_IN * N_POS + (size_t)p0;
            #pragma unroll
            for (int it2 = 0; it2 < 32; it2++) {
                int idx = it2 * 256 + tid;
                int c = idx >> 7, p = idx & 127;
                int gp = p0 + p;
                Asf[idx] = (gp < N_POS) ? xb[(size_t)c * N_POS + p] : 0.0f;
            }
        }
        __syncthreads();   // staging done; also prev iter's ldmatrix done w/ Ah/Al

        // --- convert: Ah/Al [p][c] bf16, swizzled ---
        #pragma unroll
        for (int blk = 0; blk < 4; blk++) {
            int cb = cc0 + blk * 8;
            float xv[8];
            #pragma unroll
            for (int j = 0; j < 8; j++) xv[j] = Asf[(cb + j) * TILE_P + cp];
            uint32_t hi[4], lo[4];
            #pragma unroll
            for (int q = 0; q < 4; q++) {
                float x0 = xv[2 * q], x1 = xv[2 * q + 1];
                uint32_t h = bf16x2_of(x1, x0);
                float h0 = __uint_as_float(h << 16);
                float h1 = __uint_as_float(h & 0xFFFF0000u);
                hi[q] = h;
                lo[q] = bf16x2_of(x1 - h1, x0 - h0);
            }
            uint32_t off = swz((uint32_t)(cp * 128 + cb * 2));
            *(uint4*)(sm + SM_AH + off) = make_uint4(hi[0], hi[1], hi[2], hi[3]);
            *(uint4*)(sm + SM_AL + off) = make_uint4(lo[0], lo[1], lo[2], lo[3]);
        }
        __syncthreads();

        // --- MMA: 3 segments x 4 k16-chunks ---
        float d[2][14][4];
        #pragma unroll
        for (int mt = 0; mt < 2; mt++)
            #pragma unroll
            for (int nt = 0; nt < 14; nt++)
                #pragma unroll
                for (int q = 0; q < 4; q++) d[mt][nt][q] = 0.0f;

        #pragma unroll
        for (int s = 0; s < 3; s++) {
            const uint32_t abase = smb + (s == 1 ? SM_AL : SM_AH);
            const uint32_t bbase = smb + (s == 2 ? SM_WL : SM_WH);
            #pragma unroll
            for (int kci = 0; kci < 4; kci++) {
                const uint32_t kcb = kci * 32;
                uint32_t afr[2][4];
                ldsm_x4(afr[0], abase + swz(a_lane + kcb));
                ldsm_x4(afr[1], abase + swz(a_lane + 2048 + kcb));
                #pragma unroll
                for (int nt = 0; nt < 14; nt++) {
                    uint32_t bfr[2];
                    ldsm_x2(bfr, bbase + swz(b_lane + (uint32_t)nt * 1024 + kcb));
                    mma_bf16(d[0][nt], afr[0], bfr);
                    mma_bf16(d[1][nt], afr[1], bfr);
                }
            }
        }

        // --- epilogue: bias + STG.64 ---
        {
            const int qrow = l >> 2;
            const int ncol = wn * 112 + (l & 3) * 2;
            #pragma unroll
            for (int mt = 0; mt < 2; mt++) {
                #pragma unroll
                for (int rsel = 0; rsel < 2; rsel++) {
                    int gp = p0 + wm * 32 + mt * 16 + rsel * 8 + qrow;
                    if (gp < N_POS) {
                        float* yr = yb + (size_t)gp * K_CH + ncol;
                        #pragma unroll
                        for (int nt = 0; nt < 14; nt++) {
                            float2 v;
                            v.x = d[mt][nt][rsel * 2 + 0] + bb[nt].x;
                            v.y = d[mt][nt][rsel * 2 + 1] + bb[nt].y;
                            *(float2*)(yr + nt * 8) = v;
                        }
                    }
                }
            }
        }
        __syncthreads();   // all reads of Asf/Ah/Al done before next overwrite
    }
}

// ---------------------------------------------------------------------------
// Kernel 2: gather + pair-average + transpose (unchanged from R3: 165us)
// ---------------------------------------------------------------------------
#define GM 256

__global__ void __launch_bounds__(256)
gather_kernel(const int* __restrict__ top,
              const int* __restrict__ down,
              float* __restrict__ out)
{
    __shared__ float smx[GM][33];
    const int b    = blockIdx.y;
    const int m0   = blockIdx.x * GM;
    const int tid  = threadIdx.x;
    const int lane = tid & 31;
    const int w    = tid >> 5;
    const int g8   = lane >> 3;
    const int l8   = lane & 7;

    const float* yb = g_y + (size_t)b * N_POS * K_CH;

    #pragma unroll
    for (int i = 0; i < 8; i++) {
        int mm = w * 32 + i * 4 + g8;
        int m  = m0 + mm;
        float4 v = make_float4(0.f, 0.f, 0.f, 0.f);
        if (m < NEW_N) {
            if (m < N_POS) {
                int j   = __ldg(top + m);
                int sub = j / N_POS;
                int p   = j - sub * N_POS;
                v = *(const float4*)(yb + (size_t)p * K_CH + sub * 32 + l8 * 4);
            } else {
                int2 jj = *(const int2*)(down + 2 * (m - N_POS));
                int s0 = jj.x / N_POS, p0i = jj.x - s0 * N_POS;
                int s1 = jj.y / N_POS, p1i = jj.y - s1 * N_POS;
                float4 v0 = *(const float4*)(yb + (size_t)p0i * K_CH + s0 * 32 + l8 * 4);
                float4 v1 = *(const float4*)(yb + (size_t)p1i * K_CH + s1 * 32 + l8 * 4);
                v.x = 0.5f * (v0.x + v1.x);
                v.y = 0.5f * (v0.y + v1.y);
                v.z = 0.5f * (v0.z + v1.z);
                v.w = 0.5f * (v0.w + v1.w);
            }
        }
        float* s = &smx[mm][l8 * 4];
        s[0] = v.x; s[1] = v.y; s[2] = v.z; s[3] = v.w;
    }
    __syncthreads();

    float* ob = out + (size_t)b * C_OUT * NEW_N;
    #pragma unroll
    for (int it = 0; it < C_OUT * (GM / 2) / 256; it++) {
        int idx = it * 256 + tid;
        int o = idx >> 7;
        int q = idx & 127;
        int m = m0 + 2 * q;
        if (m < NEW_N) {
            float2 v = make_float2(smx[2 * q][o], smx[2 * q + 1][o]);
            *(float2*)(ob + (size_t)o * NEW_N + m) = v;
        }
    }
}

// ---------------------------------------------------------------------------
extern "C" void kernel_launch(void* const* d_in, const int* in_sizes, int n_in,
                              void* d_out, int out_size)
{
    const float* x    = (const float*)d_in[0];
    const float* W    = (const float*)d_in[1];
    const float* bias = (const float*)d_in[2];
    const int*   top  = (const int*)d_in[3];
    const int*   down = (const int*)d_in[4];
    float* out = (float*)d_out;

    cudaFuncSetAttribute(gemm_hmma_kernel,
                         cudaFuncAttributeMaxDynamicSharedMemorySize, SM_TOTAL);

    gemm_hmma_kernel<<<GEMM_GRID, 256, SM_TOTAL>>>(x, W, bias);

    dim3 g2((NEW_N + GM - 1) / GM, B_SZ);   // (641, 16)
    gather_kernel<<<g2, 256>>>(top, down, out);
}

// round 6
// speedup vs baseline: 2.8935x; 1.0380x over previous
#include <cuda_runtime.h>
#include <cstdint>

#define B_SZ    16
#define C_IN    64
#define N_POS   40962
#define C_OUT   32
#define K_CH    224                 // 7*C_OUT, permuted: k = sub*32 + o
#define NEW_N   (4*N_POS - 6)       // 163842
#define TILE_P  128
#define TILES_PER_B 321             // ceil(40962/128)
#define WORK_ITEMS (B_SZ * TILES_PER_B)   // 5136
#define GEMM_GRID 148
#define GEMM_THREADS 512

// 587 MB scratch for y' [B][N][224] (permuted channel layout)
__device__ float g_y[(size_t)B_SZ * N_POS * K_CH];

// ---------------------------------------------------------------------------
// smem layout (bytes). All bf16 tiles are [row][64] = 128 B/row, SW128 swizzle.
// ---------------------------------------------------------------------------
#define SM_AH   0        // Ah [128][64] bf16 : 16384
#define SM_AL   16384    // Al [128][64] bf16 : 16384
#define SM_WH   32768    // Wh [224][64] bf16 : 28672
#define SM_WL   61440    // Wl [224][64] bf16 : 28672
#define SM_ASF  90112    // x staging f32 [64][128] : 32768
#define SM_TOTAL 122880

static __device__ __forceinline__ uint32_t smem_u32(const void* p) {
    uint32_t a;
    asm("{ .reg .u64 t; cvta.to.shared.u64 t, %1; cvt.u32.u64 %0, t; }" : "=r"(a) : "l"(p));
    return a;
}
static __device__ __forceinline__ uint32_t swz(uint32_t off) {
    return off ^ ((off >> 3) & 0x70);
}
static __device__ __forceinline__ uint32_t bf16x2_of(float hi_f, float lo_f) {
    uint32_t r;
    asm("cvt.rn.bf16x2.f32 %0, %1, %2;" : "=r"(r) : "f"(hi_f), "f"(lo_f));
    return r;
}
static __device__ __forceinline__ void ldsm_x4(uint32_t* a, uint32_t addr) {
    asm volatile("ldmatrix.sync.aligned.m8n8.x4.shared.b16 {%0,%1,%2,%3}, [%4];"
                 : "=r"(a[0]), "=r"(a[1]), "=r"(a[2]), "=r"(a[3]) : "r"(addr));
}
static __device__ __forceinline__ void ldsm_x2(uint32_t* b, uint32_t addr) {
    asm volatile("ldmatrix.sync.aligned.m8n8.x2.shared.b16 {%0,%1}, [%2];"
                 : "=r"(b[0]), "=r"(b[1]) : "r"(addr));
}
static __device__ __forceinline__ void mma_bf16(float* d, const uint32_t* a, const uint32_t* b) {
    asm volatile("mma.sync.aligned.m16n8k16.row.col.f32.bf16.bf16.f32 "
                 "{%0,%1,%2,%3}, {%4,%5,%6,%7}, {%8,%9}, {%0,%1,%2,%3};"
                 : "+f"(d[0]), "+f"(d[1]), "+f"(d[2]), "+f"(d[3])
                 : "r"(a[0]), "r"(a[1]), "r"(a[2]), "r"(a[3]), "r"(b[0]), "r"(b[1]));
}

// ---------------------------------------------------------------------------
// Persistent HMMA GEMM: y'[b][p][n] = sum_c x[b][c][p]*W'[n][c] + bias(n)
// 3xBF16 split over segments s: A = {Ah, Al, Ah}, B = {Wh, Wh, Wl}.
// 512 threads, 16 warps: wm = w&3 -> rows wm*32..+31 (2 m16 tiles);
// wn = w>>2 (0..3) -> cols wn*56..+55 (7 n8 tiles). Acc d[2][7][4].
// Next tile's x staged during MMA (Asf is dead after convert).
// ---------------------------------------------------------------------------
__global__ void __launch_bounds__(GEMM_THREADS, 1)
gemm_hmma_kernel(const float* __restrict__ x,
                 const float* __restrict__ W,
                 const float* __restrict__ bias)
{
    extern __shared__ char sm[];
    const uint32_t smb = smem_u32(sm);
    float* Asf = (float*)(sm + SM_ASF);

    const int tid = threadIdx.x;
    const int w   = tid >> 5;
    const int l   = tid & 31;
    const int wm  = w & 3;
    const int wn  = w >> 2;          // 0..3

    // --- one-time: build Wh/Wl (permuted, bf16 hi/lo, swizzled) ---
    for (int idx = tid; idx < K_CH * C_IN; idx += GEMM_THREADS) {
        int n = idx >> 6, c = idx & 63;
        int rw = (n & 31) * 7 + (n >> 5);
        float wv = W[rw * C_IN + c];
        uint32_t hb = bf16x2_of(0.0f, wv);              // low 16 = bf16(wv)
        float hf = __uint_as_float(hb << 16);
        uint32_t lb = bf16x2_of(0.0f, wv - hf);
        uint32_t off = swz((uint32_t)(n * 128 + c * 2));
        *(uint16_t*)(sm + SM_WH + off) = (uint16_t)hb;
        *(uint16_t*)(sm + SM_WL + off) = (uint16_t)lb;
    }

    // --- per-thread bias regs: n = wn*56 + nt*8 + 2*(l&3) ---
    float2 bb[7];
    {
        int nbase = wn * 56 + (l & 3) * 2;
        #pragma unroll
        for (int nt = 0; nt < 7; nt++) {
            int n0 = nbase + nt * 8;
            int r0 = (n0 & 31) * 7 + (n0 >> 5);
            int n1 = n0 + 1;
            int r1 = (n1 & 31) * 7 + (n1 >> 5);
            bb[nt].x = bias[r0];
            bb[nt].y = bias[r1];
        }
    }

    // ldmatrix per-lane base offsets (unswizzled)
    const uint32_t a_lane = (uint32_t)((wm * 32 + (l & 15)) * 128 + (l >> 4) * 16);
    const uint32_t b_lane = (uint32_t)((wn * 56 + (l & 7)) * 128 + ((l >> 3) & 1) * 16);

    // convert-phase mapping: thread -> row cp = tid&127, c range (tid>>7)*16
    const int cp  = tid & 127;
    const int cc0 = (tid >> 7) * 16;

    int item = blockIdx.x;

    // prologue: stage first tile
    {
        int b = item / TILES_PER_B, t = item - (item / TILES_PER_B) * TILES_PER_B;
        const float* xb = x + (size_t)b * C_IN * N_POS + (size_t)t * TILE_P;
        int p0 = t * TILE_P;
        #pragma unroll
        for (int it2 = 0; it2 < 16; it2++) {
            int idx = it2 * GEMM_THREADS + tid;
            int c = idx >> 7, p = idx & 127;
            Asf[idx] = (p0 + p < N_POS) ? xb[(size_t)c * N_POS + p] : 0.0f;
        }
    }
    __syncthreads();

    for (; item < WORK_ITEMS; item += GEMM_GRID) {
        const int b  = item / TILES_PER_B;
        const int t  = item - b * TILES_PER_B;
        const int p0 = t * TILE_P;
        float* yb = g_y + (size_t)b * N_POS * K_CH;

        // --- convert: Ah/Al [p][c] bf16, swizzled (reads Asf) ---
        #pragma unroll
        for (int blk = 0; blk < 2; blk++) {
            int cb = cc0 + blk * 8;
            float xv[8];
            #pragma unroll
            for (int j = 0; j < 8; j++) xv[j] = Asf[(cb + j) * TILE_P + cp];
            uint32_t hi[4], lo[4];
            #pragma unroll
            for (int q = 0; q < 4; q++) {
                float x0 = xv[2 * q], x1 = xv[2 * q + 1];
                uint32_t h = bf16x2_of(x1, x0);
                float h0 = __uint_as_float(h << 16);
                float h1 = __uint_as_float(h & 0xFFFF0000u);
                hi[q] = h;
                lo[q] = bf16x2_of(x1 - h1, x0 - h0);
            }
            uint32_t off = swz((uint32_t)(cp * 128 + cb * 2));
            *(uint4*)(sm + SM_AH + off) = make_uint4(hi[0], hi[1], hi[2], hi[3]);
            *(uint4*)(sm + SM_AL + off) = make_uint4(lo[0], lo[1], lo[2], lo[3]);
        }
        __syncthreads();   // Ah/Al ready; Asf reads complete -> prefetch may overwrite

        // --- prefetch next tile's x into Asf (overlaps MMA + store) ---
        {
            int nxt = item + GEMM_GRID;
            if (nxt < WORK_ITEMS) {
                int nb = nxt / TILES_PER_B, ntl = nxt - nb * TILES_PER_B;
                const float* xb = x + (size_t)nb * C_IN * N_POS + (size_t)ntl * TILE_P;
                int np0 = ntl * TILE_P;
                #pragma unroll
                for (int it2 = 0; it2 < 16; it2++) {
                    int idx = it2 * GEMM_THREADS + tid;
                    int c = idx >> 7, p = idx & 127;
                    Asf[idx] = (np0 + p < N_POS) ? xb[(size_t)c * N_POS + p] : 0.0f;
                }
            }
        }

        // --- MMA: 3 segments x 4 k16-chunks ---
        float d[2][7][4];
        #pragma unroll
        for (int mt = 0; mt < 2; mt++)
            #pragma unroll
            for (int nt = 0; nt < 7; nt++)
                #pragma unroll
                for (int q = 0; q < 4; q++) d[mt][nt][q] = 0.0f;

        #pragma unroll
        for (int s = 0; s < 3; s++) {
            const uint32_t abase = smb + (s == 1 ? SM_AL : SM_AH);
            const uint32_t bbase = smb + (s == 2 ? SM_WL : SM_WH);
            #pragma unroll
            for (int kci = 0; kci < 4; kci++) {
                const uint32_t kcb = kci * 32;
                uint32_t bfr[7][2];
                #pragma unroll
                for (int nt = 0; nt < 7; nt++)
                    ldsm_x2(bfr[nt], bbase + swz(b_lane + (uint32_t)nt * 1024 + kcb));
                uint32_t afr[2][4];
                ldsm_x4(afr[0], abase + swz(a_lane + kcb));
                ldsm_x4(afr[1], abase + swz(a_lane + 2048 + kcb));
                #pragma unroll
                for (int nt = 0; nt < 7; nt++) {
                    mma_bf16(d[0][nt], afr[0], bfr[nt]);
                    mma_bf16(d[1][nt], afr[1], bfr[nt]);
                }
            }
        }

        // --- epilogue: bias + STG.64 ---
        {
            const int qrow = l >> 2;
            const int ncol = wn * 56 + (l & 3) * 2;
            #pragma unroll
            for (int mt = 0; mt < 2; mt++) {
                #pragma unroll
                for (int rsel = 0; rsel < 2; rsel++) {
                    int gp = p0 + wm * 32 + mt * 16 + rsel * 8 + qrow;
                    if (gp < N_POS) {
                        float* yr = yb + (size_t)gp * K_CH + ncol;
                        #pragma unroll
                        for (int nt = 0; nt < 7; nt++) {
                            float2 v;
                            v.x = d[mt][nt][rsel * 2 + 0] + bb[nt].x;
                            v.y = d[mt][nt][rsel * 2 + 1] + bb[nt].y;
                            *(float2*)(yr + nt * 8) = v;
                        }
                    }
                }
            }
        }
        __syncthreads();   // ldsm of Ah/Al done; Asf prefetch visible for next convert
    }
}

// ---------------------------------------------------------------------------
// Kernel 2: gather + pair-average + transpose (unchanged from R3: 165us)
// ---------------------------------------------------------------------------
#define GM 256

__global__ void __launch_bounds__(256)
gather_kernel(const int* __restrict__ top,
              const int* __restrict__ down,
              float* __restrict__ out)
{
    __shared__ float smx[GM][33];
    const int b    = blockIdx.y;
    const int m0   = blockIdx.x * GM;
    const int tid  = threadIdx.x;
    const int lane = tid & 31;
    const int w    = tid >> 5;
    const int g8   = lane >> 3;
    const int l8   = lane & 7;

    const float* yb = g_y + (size_t)b * N_POS * K_CH;

    #pragma unroll
    for (int i = 0; i < 8; i++) {
        int mm = w * 32 + i * 4 + g8;
        int m  = m0 + mm;
        float4 v = make_float4(0.f, 0.f, 0.f, 0.f);
        if (m < NEW_N) {
            if (m < N_POS) {
                int j   = __ldg(top + m);
                int sub = j / N_POS;
                int p   = j - sub * N_POS;
                v = *(const float4*)(yb + (size_t)p * K_CH + sub * 32 + l8 * 4);
            } else {
                int2 jj = *(const int2*)(down + 2 * (m - N_POS));
                int s0 = jj.x / N_POS, p0i = jj.x - s0 * N_POS;
                int s1 = jj.y / N_POS, p1i = jj.y - s1 * N_POS;
                float4 v0 = *(const float4*)(yb + (size_t)p0i * K_CH + s0 * 32 + l8 * 4);
                float4 v1 = *(const float4*)(yb + (size_t)p1i * K_CH + s1 * 32 + l8 * 4);
                v.x = 0.5f * (v0.x + v1.x);
                v.y = 0.5f * (v0.y + v1.y);
                v.z = 0.5f * (v0.z + v1.z);
                v.w = 0.5f * (v0.w + v1.w);
            }
        }
        float* s = &smx[mm][l8 * 4];
        s[0] = v.x; s[1] = v.y; s[2] = v.z; s[3] = v.w;
    }
    __syncthreads();

    float* ob = out + (size_t)b * C_OUT * NEW_N;
    #pragma unroll
    for (int it = 0; it < C_OUT * (GM / 2) / 256; it++) {
        int idx = it * 256 + tid;
        int o = idx >> 7;
        int q = idx & 127;
        int m = m0 + 2 * q;
        if (m < NEW_N) {
            float2 v = make_float2(smx[2 * q][o], smx[2 * q + 1][o]);
            *(float2*)(ob + (size_t)o * NEW_N + m) = v;
        }
    }
}

// ---------------------------------------------------------------------------
extern "C" void kernel_launch(void* const* d_in, const int* in_sizes, int n_in,
                              void* d_out, int out_size)
{
    const float* x    = (const float*)d_in[0];
    const float* W    = (const float*)d_in[1];
    const float* bias = (const float*)d_in[2];
    const int*   top  = (const int*)d_in[3];
    const int*   down = (const int*)d_in[4];
    float* out = (float*)d_out;

    cudaFuncSetAttribute(gemm_hmma_kernel,
                         cudaFuncAttributeMaxDynamicSharedMemorySize, SM_TOTAL);

    gemm_hmma_kernel<<<GEMM_GRID, GEMM_THREADS, SM_TOTAL>>>(x, W, bias);

    dim3 g2((NEW_N + GM - 1) / GM, B_SZ);   // (641, 16)
    gather_kernel<<<g2, 256>>>(top, down, out);
}

// round 7
// speedup vs baseline: 3.1868x; 1.1014x over previous
#include <cuda_runtime.h>
#include <cuda_fp16.h>
#include <cstdint>

#define B_SZ    16
#define C_IN    64
#define N_POS   40962
#define C_OUT   32
#define K_CH    224                 // 7*C_OUT, permuted: k = sub*32 + o
#define NEW_N   (4*N_POS - 6)       // 163842
#define TILE_P  128
#define TILES_PER_B 321             // ceil(40962/128)
#define WORK_ITEMS (B_SZ * TILES_PER_B)   // 5136
#define GEMM_GRID 148
#define GEMM_THREADS 512

// 293 MB scratch for y' [B][N][224] fp16 (permuted channel layout)
__device__ __half g_y[(size_t)B_SZ * N_POS * K_CH];

// ---------------------------------------------------------------------------
// smem layout (bytes). bf16 tiles are [row][64] = 128 B/row, SW128 swizzle.
// ---------------------------------------------------------------------------
#define SM_AH    0        // Ah [128][64] bf16 : 16384
#define SM_AL    16384    // Al [128][64] bf16 : 16384
#define SM_WH    32768    // Wh [224][64] bf16 : 28672
#define SM_WL    61440    // Wl [224][64] bf16 : 28672
#define SM_ASF   90112    // x staging f32 [64][128] : 32768
#define SM_STAGE 122880   // epilogue stage fp16 [128][232] : 59392 (464B rows)
#define STG_ROW_H 232     // halves per stage row (464 B = 29*16)
#define SM_TOTAL 182272

static __device__ __forceinline__ uint32_t smem_u32(const void* p) {
    uint32_t a;
    asm("{ .reg .u64 t; cvta.to.shared.u64 t, %1; cvt.u32.u64 %0, t; }" : "=r"(a) : "l"(p));
    return a;
}
static __device__ __forceinline__ uint32_t swz(uint32_t off) {
    return off ^ ((off >> 3) & 0x70);
}
static __device__ __forceinline__ uint32_t bf16x2_of(float hi_f, float lo_f) {
    uint32_t r;
    asm("cvt.rn.bf16x2.f32 %0, %1, %2;" : "=r"(r) : "f"(hi_f), "f"(lo_f));
    return r;
}
static __device__ __forceinline__ void ldsm_x4(uint32_t* a, uint32_t addr) {
    asm volatile("ldmatrix.sync.aligned.m8n8.x4.shared.b16 {%0,%1,%2,%3}, [%4];"
                 : "=r"(a[0]), "=r"(a[1]), "=r"(a[2]), "=r"(a[3]) : "r"(addr));
}
static __device__ __forceinline__ void ldsm_x2(uint32_t* b, uint32_t addr) {
    asm volatile("ldmatrix.sync.aligned.m8n8.x2.shared.b16 {%0,%1}, [%2];"
                 : "=r"(b[0]), "=r"(b[1]) : "r"(addr));
}
static __device__ __forceinline__ void mma_bf16(float* d, const uint32_t* a, const uint32_t* b) {
    asm volatile("mma.sync.aligned.m16n8k16.row.col.f32.bf16.bf16.f32 "
                 "{%0,%1,%2,%3}, {%4,%5,%6,%7}, {%8,%9}, {%0,%1,%2,%3};"
                 : "+f"(d[0]), "+f"(d[1]), "+f"(d[2]), "+f"(d[3])
                 : "r"(a[0]), "r"(a[1]), "r"(a[2]), "r"(a[3]), "r"(b[0]), "r"(b[1]));
}

// ---------------------------------------------------------------------------
// Persistent HMMA GEMM: y'[b][p][n] = sum_c x[b][c][p]*W'[n][c] + bias(n)
// 3xBF16 split: segments {Ah*Wh, Al*Wh, Ah*Wl}. 512 threads / 16 warps.
// wm = w&3 -> rows wm*32..+31; wn = w>>2 -> cols wn*56..+55. Acc d[2][7][4].
// Epilogue: f32+bias -> fp16 -> smem stage -> coalesced STG.128 rows.
// ---------------------------------------------------------------------------
__global__ void __launch_bounds__(GEMM_THREADS, 1)
gemm_hmma_kernel(const float* __restrict__ x,
                 const float* __restrict__ W,
                 const float* __restrict__ bias)
{
    extern __shared__ char sm[];
    const uint32_t smb = smem_u32(sm);
    float*  Asf = (float*)(sm + SM_ASF);
    __half* stg = (__half*)(sm + SM_STAGE);

    const int tid = threadIdx.x;
    const int w   = tid >> 5;
    const int l   = tid & 31;
    const int wm  = w & 3;
    const int wn  = w >> 2;          // 0..3

    // --- one-time: build Wh/Wl (permuted, bf16 hi/lo, swizzled) ---
    for (int idx = tid; idx < K_CH * C_IN; idx += GEMM_THREADS) {
        int n = idx >> 6, c = idx & 63;
        int rw = (n & 31) * 7 + (n >> 5);
        float wv = W[rw * C_IN + c];
        uint32_t hb = bf16x2_of(0.0f, wv);              // low 16 = bf16(wv)
        float hf = __uint_as_float(hb << 16);
        uint32_t lb = bf16x2_of(0.0f, wv - hf);
        uint32_t off = swz((uint32_t)(n * 128 + c * 2));
        *(uint16_t*)(sm + SM_WH + off) = (uint16_t)hb;
        *(uint16_t*)(sm + SM_WL + off) = (uint16_t)lb;
    }

    // --- per-thread bias regs: n = wn*56 + nt*8 + 2*(l&3) ---
    float2 bb[7];
    {
        int nbase = wn * 56 + (l & 3) * 2;
        #pragma unroll
        for (int nt = 0; nt < 7; nt++) {
            int n0 = nbase + nt * 8;
            int r0 = (n0 & 31) * 7 + (n0 >> 5);
            int n1 = n0 + 1;
            int r1 = (n1 & 31) * 7 + (n1 >> 5);
            bb[nt].x = bias[r0];
            bb[nt].y = bias[r1];
        }
    }

    // ldmatrix per-lane base offsets (unswizzled)
    const uint32_t a_lane = (uint32_t)((wm * 32 + (l & 15)) * 128 + (l >> 4) * 16);
    const uint32_t b_lane = (uint32_t)((wn * 56 + (l & 7)) * 128 + ((l >> 3) & 1) * 16);

    // convert-phase mapping: thread -> row cp = tid&127, c range (tid>>7)*16
    const int cp  = tid & 127;
    const int cc0 = (tid >> 7) * 16;

    int item = blockIdx.x;

    // prologue: stage first tile
    {
        int b = item / TILES_PER_B, t = item - (item / TILES_PER_B) * TILES_PER_B;
        const float* xb = x + (size_t)b * C_IN * N_POS + (size_t)t * TILE_P;
        int p0 = t * TILE_P;
        #pragma unroll
        for (int it2 = 0; it2 < 16; it2++) {
            int idx = it2 * GEMM_THREADS + tid;
            int c = idx >> 7, p = idx & 127;
            Asf[idx] = (p0 + p < N_POS) ? xb[(size_t)c * N_POS + p] : 0.0f;
        }
    }
    __syncthreads();

    for (; item < WORK_ITEMS; item += GEMM_GRID) {
        const int b  = item / TILES_PER_B;
        const int t  = item - b * TILES_PER_B;
        const int p0 = t * TILE_P;
        __half* yb = g_y + (size_t)b * N_POS * K_CH;

        // --- convert: Ah/Al [p][c] bf16, swizzled (reads Asf) ---
        #pragma unroll
        for (int blk = 0; blk < 2; blk++) {
            int cb = cc0 + blk * 8;
            float xv[8];
            #pragma unroll
            for (int j = 0; j < 8; j++) xv[j] = Asf[(cb + j) * TILE_P + cp];
            uint32_t hi[4], lo[4];
            #pragma unroll
            for (int q = 0; q < 4; q++) {
                float x0 = xv[2 * q], x1 = xv[2 * q + 1];
                uint32_t h = bf16x2_of(x1, x0);
                float h0 = __uint_as_float(h << 16);
                float h1 = __uint_as_float(h & 0xFFFF0000u);
                hi[q] = h;
                lo[q] = bf16x2_of(x1 - h1, x0 - h0);
            }
            uint32_t off = swz((uint32_t)(cp * 128 + cb * 2));
            *(uint4*)(sm + SM_AH + off) = make_uint4(hi[0], hi[1], hi[2], hi[3]);
            *(uint4*)(sm + SM_AL + off) = make_uint4(lo[0], lo[1], lo[2], lo[3]);
        }
        __syncthreads();   // Ah/Al ready; Asf reads complete

        // --- prefetch next tile's x into Asf (overlaps MMA + epilogue) ---
        {
            int nxt = item + GEMM_GRID;
            if (nxt < WORK_ITEMS) {
                int nb = nxt / TILES_PER_B, ntl = nxt - nb * TILES_PER_B;
                const float* xb = x + (size_t)nb * C_IN * N_POS + (size_t)ntl * TILE_P;
                int np0 = ntl * TILE_P;
                #pragma unroll
                for (int it2 = 0; it2 < 16; it2++) {
                    int idx = it2 * GEMM_THREADS + tid;
                    int c = idx >> 7, p = idx & 127;
                    Asf[idx] = (np0 + p < N_POS) ? xb[(size_t)c * N_POS + p] : 0.0f;
                }
            }
        }

        // --- MMA: 3 segments x 4 k16-chunks ---
        float d[2][7][4];
        #pragma unroll
        for (int mt = 0; mt < 2; mt++)
            #pragma unroll
            for (int nt = 0; nt < 7; nt++)
                #pragma unroll
                for (int q = 0; q < 4; q++) d[mt][nt][q] = 0.0f;

        #pragma unroll
        for (int s = 0; s < 3; s++) {
            const uint32_t abase = smb + (s == 1 ? SM_AL : SM_AH);
            const uint32_t bbase = smb + (s == 2 ? SM_WL : SM_WH);
            #pragma unroll
            for (int kci = 0; kci < 4; kci++) {
                const uint32_t kcb = kci * 32;
                uint32_t bfr[7][2];
                #pragma unroll
                for (int nt = 0; nt < 7; nt++)
                    ldsm_x2(bfr[nt], bbase + swz(b_lane + (uint32_t)nt * 1024 + kcb));
                uint32_t afr[2][4];
                ldsm_x4(afr[0], abase + swz(a_lane + kcb));
                ldsm_x4(afr[1], abase + swz(a_lane + 2048 + kcb));
                #pragma unroll
                for (int nt = 0; nt < 7; nt++) {
                    mma_bf16(d[0][nt], afr[0], bfr[nt]);
                    mma_bf16(d[1][nt], afr[1], bfr[nt]);
                }
            }
        }

        // --- epilogue stage: bias + fp16 pack -> smem (conflict-free STS.32) ---
        {
            const int qrow = l >> 2;
            const int ncol = wn * 56 + (l & 3) * 2;
            #pragma unroll
            for (int mt = 0; mt < 2; mt++) {
                #pragma unroll
                for (int rsel = 0; rsel < 2; rsel++) {
                    int row = wm * 32 + mt * 16 + rsel * 8 + qrow;
                    __half* sr = stg + row * STG_ROW_H + ncol;
                    #pragma unroll
                    for (int nt = 0; nt < 7; nt++) {
                        float vx = d[mt][nt][rsel * 2 + 0] + bb[nt].x;
                        float vy = d[mt][nt][rsel * 2 + 1] + bb[nt].y;
                        *(half2*)(sr + nt * 8) = __floats2half2_rn(vx, vy);
                    }
                }
            }
        }
        __syncthreads();

        // --- coalesced writeback: warp w -> rows w*8..+7, 448B/row ---
        if (l < 28) {
            #pragma unroll
            for (int r = 0; r < 8; r++) {
                int row = w * 8 + r;
                int gp = p0 + row;
                if (gp < N_POS) {
                    uint4 v = *(const uint4*)(stg + row * STG_ROW_H + l * 8);
                    *(uint4*)(yb + (size_t)gp * K_CH + l * 8) = v;
                }
            }
        }
        __syncthreads();   // stage reads done; Asf prefetch visible for next convert
    }
}

// ---------------------------------------------------------------------------
// Kernel 2: gather + pair-average + transpose. fp16 y: 4 lanes x uint4 per m.
// ---------------------------------------------------------------------------
#define GM 256

__global__ void __launch_bounds__(256)
gather_kernel(const int* __restrict__ top,
              const int* __restrict__ down,
              float* __restrict__ out)
{
    __shared__ float smx[GM][33];
    const int b    = blockIdx.y;
    const int m0   = blockIdx.x * GM;
    const int tid  = threadIdx.x;
    const int lane = tid & 31;
    const int w    = tid >> 5;
    const int g8   = lane >> 2;    // 0..7 : which m within the octet
    const int l4   = lane & 3;     // 0..3 : uint4 slot (8 halves) of 32 channels

    const __half* yb = g_y + (size_t)b * N_POS * K_CH;

    #pragma unroll
    for (int i = 0; i < 4; i++) {
        int mm = w * 32 + i * 8 + g8;
        int m  = m0 + mm;
        float vf[8];
        #pragma unroll
        for (int j = 0; j < 8; j++) vf[j] = 0.0f;
        if (m < NEW_N) {
            if (m < N_POS) {
                int j   = __ldg(top + m);
                int sub = j / N_POS;
                int p   = j - sub * N_POS;
                uint4 v = *(const uint4*)(yb + (size_t)p * K_CH + sub * 32 + l4 * 8);
                const half2* h = (const half2*)&v;
                #pragma unroll
                for (int q = 0; q < 4; q++) {
                    float2 f = __half22float2(h[q]);
                    vf[2 * q] = f.x; vf[2 * q + 1] = f.y;
                }
            } else {
                int2 jj = *(const int2*)(down + 2 * (m - N_POS));
                int s0 = jj.x / N_POS, p0i = jj.x - s0 * N_POS;
                int s1 = jj.y / N_POS, p1i = jj.y - s1 * N_POS;
                uint4 v0 = *(const uint4*)(yb + (size_t)p0i * K_CH + s0 * 32 + l4 * 8);
                uint4 v1 = *(const uint4*)(yb + (size_t)p1i * K_CH + s1 * 32 + l4 * 8);
                const half2* h0 = (const half2*)&v0;
                const half2* h1 = (const half2*)&v1;
                #pragma unroll
                for (int q = 0; q < 4; q++) {
                    float2 f0 = __half22float2(h0[q]);
                    float2 f1 = __half22float2(h1[q]);
                    vf[2 * q]     = 0.5f * (f0.x + f1.x);
                    vf[2 * q + 1] = 0.5f * (f0.y + f1.y);
                }
            }
        }
        float* s = &smx[mm][l4 * 8];
        #pragma unroll
        for (int j = 0; j < 8; j++) s[j] = vf[j];
    }
    __syncthreads();

    float* ob = out + (size_t)b * C_OUT * NEW_N;
    #pragma unroll
    for (int it = 0; it < C_OUT * (GM / 2) / 256; it++) {
        int idx = it * 256 + tid;
        int o = idx >> 7;
        int q = idx & 127;
        int m = m0 + 2 * q;
        if (m < NEW_N) {
            float2 v = make_float2(smx[2 * q][o], smx[2 * q + 1][o]);
            *(float2*)(ob + (size_t)o * NEW_N + m) = v;
        }
    }
}

// ---------------------------------------------------------------------------
extern "C" void kernel_launch(void* const* d_in, const int* in_sizes, int n_in,
                              void* d_out, int out_size)
{
    const float* x    = (const float*)d_in[0];
    const float* W    = (const float*)d_in[1];
    const float* bias = (const float*)d_in[2];
    const int*   top  = (const int*)d_in[3];
    const int*   down = (const int*)d_in[4];
    float* out = (float*)d_out;

    cudaFuncSetAttribute(gemm_hmma_kernel,
                         cudaFuncAttributeMaxDynamicSharedMemorySize, SM_TOTAL);

    gemm_hmma_kernel<<<GEMM_GRID, GEMM_THREADS, SM_TOTAL>>>(x, W, bias);

    dim3 g2((NEW_N + GM - 1) / GM, B_SZ);   // (641, 16)
    gather_kernel<<<g2, 256>>>(top, down, out);
}

// round 8
// speedup vs baseline: 3.8353x; 1.2035x over previous
#include <cuda_runtime.h>
#include <cuda_fp16.h>
#include <cstdint>

#define B_SZ    16
#define C_IN    64
#define N_POS   40962
#define C_OUT   32
#define K_CH    224                 // 7*C_OUT, permuted: k = sub*32 + o
#define NEW_N   (4*N_POS - 6)       // 163842
#define TILE_P  128
#define TILES_PER_B 321             // ceil(40962/128)
#define WORK_ITEMS (B_SZ * TILES_PER_B)   // 5136
#define GEMM_GRID 148
#define GEMM_THREADS 512

// 293 MB scratch for y' [B][N][224] fp16 (permuted channel layout)
__device__ __half g_y[(size_t)B_SZ * N_POS * K_CH];

// ---------------------------------------------------------------------------
// smem layout (bytes). fp16 tiles are [row][64] = 128 B/row, SW128 swizzle.
// ---------------------------------------------------------------------------
#define SM_AH    0        // xh [128][64] fp16 : 16384
#define SM_AL    16384    // xl [128][64] fp16 : 16384
#define SM_WH    32768    // wh [224][64] fp16 : 28672
#define SM_ASF   61440    // x staging f32 [64][128] : 32768
#define SM_STAGE 94208    // epilogue stage fp16 [128][232] : 59392 (464B rows)
#define STG_ROW_H 232     // halves per stage row (464 B = 29*16)
#define SM_TOTAL 153600

static __device__ __forceinline__ uint32_t smem_u32(const void* p) {
    uint32_t a;
    asm("{ .reg .u64 t; cvta.to.shared.u64 t, %1; cvt.u32.u64 %0, t; }" : "=r"(a) : "l"(p));
    return a;
}
static __device__ __forceinline__ uint32_t swz(uint32_t off) {
    return off ^ ((off >> 3) & 0x70);
}
static __device__ __forceinline__ void ldsm_x4(uint32_t* a, uint32_t addr) {
    asm volatile("ldmatrix.sync.aligned.m8n8.x4.shared.b16 {%0,%1,%2,%3}, [%4];"
                 : "=r"(a[0]), "=r"(a[1]), "=r"(a[2]), "=r"(a[3]) : "r"(addr));
}
static __device__ __forceinline__ void ldsm_x2(uint32_t* b, uint32_t addr) {
    asm volatile("ldmatrix.sync.aligned.m8n8.x2.shared.b16 {%0,%1}, [%2];"
                 : "=r"(b[0]), "=r"(b[1]) : "r"(addr));
}
static __device__ __forceinline__ void mma_f16(float* d, const uint32_t* a, const uint32_t* b) {
    asm volatile("mma.sync.aligned.m16n8k16.row.col.f32.f16.f16.f32 "
                 "{%0,%1,%2,%3}, {%4,%5,%6,%7}, {%8,%9}, {%0,%1,%2,%3};"
                 : "+f"(d[0]), "+f"(d[1]), "+f"(d[2]), "+f"(d[3])
                 : "r"(a[0]), "r"(a[1]), "r"(a[2]), "r"(a[3]), "r"(b[0]), "r"(b[1]));
}

// ---------------------------------------------------------------------------
// Persistent HMMA GEMM: y'[b][p][n] = sum_c x[b][c][p]*W'[n][c] + bias(n)
// fp16 2-segment split: y = xh*wh + xl*wh (w single fp16; err ~1.4e-4).
// 512 threads / 16 warps. wm=w&3 -> rows wm*32..+31; wn=w>>2 -> cols
// wn*56..+55. Acc d[2][7][4]. B fragments shared across both segments.
// ---------------------------------------------------------------------------
__global__ void __launch_bounds__(GEMM_THREADS, 1)
gemm_hmma_kernel(const float* __restrict__ x,
                 const float* __restrict__ W,
                 const float* __restrict__ bias)
{
    extern __shared__ char sm[];
    const uint32_t smb = smem_u32(sm);
    float*  Asf = (float*)(sm + SM_ASF);
    __half* stg = (__half*)(sm + SM_STAGE);

    const int tid = threadIdx.x;
    const int w   = tid >> 5;
    const int l   = tid & 31;
    const int wm  = w & 3;
    const int wn  = w >> 2;          // 0..3

    // --- one-time: build wh (permuted, fp16, swizzled) ---
    for (int idx = tid; idx < K_CH * C_IN; idx += GEMM_THREADS) {
        int n = idx >> 6, c = idx & 63;
        int rw = (n & 31) * 7 + (n >> 5);
        float wv = W[rw * C_IN + c];
        uint32_t off = swz((uint32_t)(n * 128 + c * 2));
        *(__half*)(sm + SM_WH + off) = __float2half_rn(wv);
    }

    // --- per-thread bias regs: n = wn*56 + nt*8 + 2*(l&3) ---
    float2 bb[7];
    {
        int nbase = wn * 56 + (l & 3) * 2;
        #pragma unroll
        for (int nt = 0; nt < 7; nt++) {
            int n0 = nbase + nt * 8;
            int r0 = (n0 & 31) * 7 + (n0 >> 5);
            int n1 = n0 + 1;
            int r1 = (n1 & 31) * 7 + (n1 >> 5);
            bb[nt].x = bias[r0];
            bb[nt].y = bias[r1];
        }
    }

    // ldmatrix per-lane base offsets (unswizzled)
    const uint32_t a_lane = (uint32_t)((wm * 32 + (l & 15)) * 128 + (l >> 4) * 16);
    const uint32_t b_lane = (uint32_t)((wn * 56 + (l & 7)) * 128 + ((l >> 3) & 1) * 16);

    // convert-phase mapping: thread -> row cp = tid&127, c range (tid>>7)*16
    const int cp  = tid & 127;
    const int cc0 = (tid >> 7) * 16;

    int item = blockIdx.x;

    // prologue: stage first tile
    {
        int b = item / TILES_PER_B, t = item - (item / TILES_PER_B) * TILES_PER_B;
        const float* xb = x + (size_t)b * C_IN * N_POS + (size_t)t * TILE_P;
        int p0 = t * TILE_P;
        #pragma unroll
        for (int it2 = 0; it2 < 16; it2++) {
            int idx = it2 * GEMM_THREADS + tid;
            int c = idx >> 7, p = idx & 127;
            Asf[idx] = (p0 + p < N_POS) ? xb[(size_t)c * N_POS + p] : 0.0f;
        }
    }
    __syncthreads();

    for (; item < WORK_ITEMS; item += GEMM_GRID) {
        const int b  = item / TILES_PER_B;
        const int t  = item - b * TILES_PER_B;
        const int p0 = t * TILE_P;
        __half* yb = g_y + (size_t)b * N_POS * K_CH;

        // --- convert: xh/xl [p][c] fp16, swizzled (reads Asf) ---
        #pragma unroll
        for (int blk = 0; blk < 2; blk++) {
            int cb = cc0 + blk * 8;
            float xv[8];
            #pragma unroll
            for (int j = 0; j < 8; j++) xv[j] = Asf[(cb + j) * TILE_P + cp];
            uint32_t hi[4], lo[4];
            #pragma unroll
            for (int q = 0; q < 4; q++) {
                float x0 = xv[2 * q], x1 = xv[2 * q + 1];
                half2 h = __floats2half2_rn(x0, x1);
                float2 hf = __half22float2(h);
                half2 lw = __floats2half2_rn(x0 - hf.x, x1 - hf.y);
                hi[q] = *(uint32_t*)&h;
                lo[q] = *(uint32_t*)&lw;
            }
            uint32_t off = swz((uint32_t)(cp * 128 + cb * 2));
            *(uint4*)(sm + SM_AH + off) = make_uint4(hi[0], hi[1], hi[2], hi[3]);
            *(uint4*)(sm + SM_AL + off) = make_uint4(lo[0], lo[1], lo[2], lo[3]);
        }
        __syncthreads();   // xh/xl ready; Asf reads complete

        // --- prefetch next tile's x into Asf (overlaps MMA + epilogue) ---
        {
            int nxt = item + GEMM_GRID;
            if (nxt < WORK_ITEMS) {
                int nb = nxt / TILES_PER_B, ntl = nxt - nb * TILES_PER_B;
                const float* xb = x + (size_t)nb * C_IN * N_POS + (size_t)ntl * TILE_P;
                int np0 = ntl * TILE_P;
                #pragma unroll
                for (int it2 = 0; it2 < 16; it2++) {
                    int idx = it2 * GEMM_THREADS + tid;
                    int c = idx >> 7, p = idx & 127;
                    Asf[idx] = (np0 + p < N_POS) ? xb[(size_t)c * N_POS + p] : 0.0f;
                }
            }
        }

        // --- MMA: 4 k16-chunks, 2 segments sharing B fragments ---
        float d[2][7][4];
        #pragma unroll
        for (int mt = 0; mt < 2; mt++)
            #pragma unroll
            for (int nt = 0; nt < 7; nt++)
                #pragma unroll
                for (int q = 0; q < 4; q++) d[mt][nt][q] = 0.0f;

        #pragma unroll
        for (int kci = 0; kci < 4; kci++) {
            const uint32_t kcb = kci * 32;
            uint32_t bfr[7][2];
            #pragma unroll
            for (int nt = 0; nt < 7; nt++)
                ldsm_x2(bfr[nt], smb + SM_WH + swz(b_lane + (uint32_t)nt * 1024 + kcb));
            uint32_t ah[2][4], al[2][4];
            ldsm_x4(ah[0], smb + SM_AH + swz(a_lane + kcb));
            ldsm_x4(ah[1], smb + SM_AH + swz(a_lane + 2048 + kcb));
            ldsm_x4(al[0], smb + SM_AL + swz(a_lane + kcb));
            ldsm_x4(al[1], smb + SM_AL + swz(a_lane + 2048 + kcb));
            #pragma unroll
            for (int nt = 0; nt < 7; nt++) {
                mma_f16(d[0][nt], ah[0], bfr[nt]);
                mma_f16(d[1][nt], ah[1], bfr[nt]);
                mma_f16(d[0][nt], al[0], bfr[nt]);
                mma_f16(d[1][nt], al[1], bfr[nt]);
            }
        }

        // --- epilogue stage: bias + fp16 pack -> smem ---
        {
            const int qrow = l >> 2;
            const int ncol = wn * 56 + (l & 3) * 2;
            #pragma unroll
            for (int mt = 0; mt < 2; mt++) {
                #pragma unroll
                for (int rsel = 0; rsel < 2; rsel++) {
                    int row = wm * 32 + mt * 16 + rsel * 8 + qrow;
                    __half* sr = stg + row * STG_ROW_H + ncol;
                    #pragma unroll
                    for (int nt = 0; nt < 7; nt++) {
                        float vx = d[mt][nt][rsel * 2 + 0] + bb[nt].x;
                        float vy = d[mt][nt][rsel * 2 + 1] + bb[nt].y;
                        *(half2*)(sr + nt * 8) = __floats2half2_rn(vx, vy);
                    }
                }
            }
        }
        __syncthreads();

        // --- coalesced writeback: warp w -> rows w*8..+7, 448B/row ---
        if (l < 28) {
            #pragma unroll
            for (int r = 0; r < 8; r++) {
                int row = w * 8 + r;
                int gp = p0 + row;
                if (gp < N_POS) {
                    uint4 v = *(const uint4*)(stg + row * STG_ROW_H + l * 8);
                    *(uint4*)(yb + (size_t)gp * K_CH + l * 8) = v;
                }
            }
        }
        __syncthreads();   // stage reads done; Asf prefetch visible for next convert
    }
}

// ---------------------------------------------------------------------------
// Kernel 2: gather + pair-average + transpose. fp16 y: 4 lanes x uint4 per m.
// ---------------------------------------------------------------------------
#define GM 256

__global__ void __launch_bounds__(256)
gather_kernel(const int* __restrict__ top,
              const int* __restrict__ down,
              float* __restrict__ out)
{
    __shared__ float smx[GM][33];
    const int b    = blockIdx.y;
    const int m0   = blockIdx.x * GM;
    const int tid  = threadIdx.x;
    const int lane = tid & 31;
    const int w    = tid >> 5;
    const int g8   = lane >> 2;    // 0..7 : which m within the octet
    const int l4   = lane & 3;     // 0..3 : uint4 slot (8 halves) of 32 channels

    const __half* yb = g_y + (size_t)b * N_POS * K_CH;

    #pragma unroll
    for (int i = 0; i < 4; i++) {
        int mm = w * 32 + i * 8 + g8;
        int m  = m0 + mm;
        float vf[8];
        #pragma unroll
        for (int j = 0; j < 8; j++) vf[j] = 0.0f;
        if (m < NEW_N) {
            if (m < N_POS) {
                int j   = __ldg(top + m);
                int sub = j / N_POS;
                int p   = j - sub * N_POS;
                uint4 v = *(const uint4*)(yb + (size_t)p * K_CH + sub * 32 + l4 * 8);
                const half2* h = (const half2*)&v;
                #pragma unroll
                for (int q = 0; q < 4; q++) {
                    float2 f = __half22float2(h[q]);
                    vf[2 * q] = f.x; vf[2 * q + 1] = f.y;
                }
            } else {
                int2 jj = *(const int2*)(down + 2 * (m - N_POS));
                int s0 = jj.x / N_POS, p0i = jj.x - s0 * N_POS;
                int s1 = jj.y / N_POS, p1i = jj.y - s1 * N_POS;
                uint4 v0 = *(const uint4*)(yb + (size_t)p0i * K_CH + s0 * 32 + l4 * 8);
                uint4 v1 = *(const uint4*)(yb + (size_t)p1i * K_CH + s1 * 32 + l4 * 8);
                const half2* h0 = (const half2*)&v0;
                const half2* h1 = (const half2*)&v1;
                #pragma unroll
                for (int q = 0; q < 4; q++) {
                    float2 f0 = __half22float2(h0[q]);
                    float2 f1 = __half22float2(h1[q]);
                    vf[2 * q]     = 0.5f * (f0.x + f1.x);
                    vf[2 * q + 1] = 0.5f * (f0.y + f1.y);
                }
            }
        }
        float* s = &smx[mm][l4 * 8];
        #pragma unroll
        for (int j = 0; j < 8; j++) s[j] = vf[j];
    }
    __syncthreads();

    float* ob = out + (size_t)b * C_OUT * NEW_N;
    #pragma unroll
    for (int it = 0; it < C_OUT * (GM / 2) / 256; it++) {
        int idx = it * 256 + tid;
        int o = idx >> 7;
        int q = idx & 127;
        int m = m0 + 2 * q;
        if (m < NEW_N) {
            float2 v = make_float2(smx[2 * q][o], smx[2 * q + 1][o]);
            *(float2*)(ob + (size_t)o * NEW_N + m) = v;
        }
    }
}

// ---------------------------------------------------------------------------
extern "C" void kernel_launch(void* const* d_in, const int* in_sizes, int n_in,
                              void* d_out, int out_size)
{
    const float* x    = (const float*)d_in[0];
    const float* W    = (const float*)d_in[1];
    const float* bias = (const float*)d_in[2];
    const int*   top  = (const int*)d_in[3];
    const int*   down = (const int*)d_in[4];
    float* out = (float*)d_out;

    cudaFuncSetAttribute(gemm_hmma_kernel,
                         cudaFuncAttributeMaxDynamicSharedMemorySize, SM_TOTAL);

    gemm_hmma_kernel<<<GEMM_GRID, GEMM_THREADS, SM_TOTAL>>>(x, W, bias);

    dim3 g2((NEW_N + GM - 1) / GM, B_SZ);   // (641, 16)
    gather_kernel<<<g2, 256>>>(top, down, out);
}